// round 1
// baseline (speedup 1.0000x reference)
#include <cuda_runtime.h>

// LSTMAnomalyDetector: B=4096, T=512, I=3, H=64
// out[b,t,:] = W_dec @ h[b,t] + b_dec,  h from standard LSTM (PyTorch gate order i,f,g,o)
//
// Persistent-CTA design: each CTA owns 32 batch rows and iterates all 512
// timesteps with h (shared), c (registers) resident on-chip.
// Recurrent matvec done with packed fp32x2 FMAs (fma.rn.f32x2), weights
// register-cached per thread (thread g owns gate-row g of W_hh).

#define B_  4096
#define T_  512
#define H_  64
#define G_  256     // 4*H
#define RT  32      // batch rows per CTA
#define NT  256     // threads per CTA (== G_)
#define GPITCH 33   // gates smem pitch (conflict-free STS from gate-major threads)

typedef unsigned long long ull;

__device__ __forceinline__ float tanhfast(float x) {
    float y;
    asm("tanh.approx.f32 %0, %1;" : "=f"(y) : "f"(x));
    return y;
}
__device__ __forceinline__ float sigf(float x) {
    return fmaf(0.5f, tanhfast(0.5f * x), 0.5f);
}
__device__ __forceinline__ ull pack2(float a, float b) {
    ull r;
    asm("mov.b64 %0, {%1, %2};" : "=l"(r) : "f"(a), "f"(b));
    return r;
}
__device__ __forceinline__ void unpack2(ull v, float& lo, float& hi) {
    asm("mov.b64 {%0, %1}, %2;" : "=f"(lo), "=f"(hi) : "l"(v));
}
// d = a*b + c on packed fp32x2 (PTX-only instruction; ptxas won't auto-fuse this)
__device__ __forceinline__ ull fma2(ull a, ull b, ull c) {
    ull d;
    asm("fma.rn.f32x2 %0, %1, %2, %3;" : "=l"(d) : "l"(a), "l"(b), "l"(c));
    return d;
}

__global__ void __launch_bounds__(NT)
lstm_persistent_kernel(const float* __restrict__ x,      // [B, T, 3]
                       const float* __restrict__ Wih,    // [256, 3]
                       const float* __restrict__ Whh,    // [256, 64]
                       const float* __restrict__ bih,    // [256]
                       const float* __restrict__ bhh,    // [256]
                       const float* __restrict__ Wdec,   // [3, 64]
                       const float* __restrict__ bdec,   // [3]
                       float* __restrict__ out)          // [B, T, 3]
{
    __shared__ __align__(16) float gates[G_ * GPITCH];   // [gate][row] pitch 33
    __shared__ __align__(16) float hsh[H_ * RT];         // [k][row]  (row-contig for f32x2 loads)
    __shared__ __align__(16) float xsh[2][3][RT];        // double-buffered x, transposed [i][row]
    __shared__ __align__(16) float wdec_s[3 * H_];

    const int tid  = threadIdx.x;
    const int row0 = blockIdx.x * RT;

    // ---- one-time setup -------------------------------------------------
    // Thread g caches W_hh[g][0..63] in registers.
    float w[H_];
#pragma unroll
    for (int k = 0; k < H_; k++) w[k] = Whh[tid * H_ + k];

    const float wi0 = Wih[tid * 3 + 0];
    const float wi1 = Wih[tid * 3 + 1];
    const float wi2 = Wih[tid * 3 + 2];
    const float bias = bih[tid] + bhh[tid];
    const ull bias2 = pack2(bias, bias);
    const ull wih2_0 = pack2(wi0, wi0);
    const ull wih2_1 = pack2(wi1, wi1);
    const ull wih2_2 = pack2(wi2, wi2);

    if (tid < 3 * H_) wdec_s[tid] = Wdec[tid];
    for (int i = tid; i < H_ * RT; i += NT) hsh[i] = 0.0f;   // h0 = 0

    float bd = 0.0f;
    if (tid < 96) {
        const int i = tid >> 5;            // output component 0..2
        const int r = tid & 31;            // row within tile
        bd = bdec[i];
        xsh[0][i][r] = x[(row0 + r) * (T_ * 3) + 0 * 3 + i];  // x(t=0)
    }

    float c[8];                            // c0 = 0 (thread owns 8 (row,unit) cells)
#pragma unroll
    for (int p = 0; p < 8; p++) c[p] = 0.0f;

    const int r_ = tid & 31;               // elementwise: my row
    const int j0 = tid >> 5;                // elementwise: my unit group base

    __syncthreads();

    // ---- timestep loop ---------------------------------------------------
    for (int t = 0; t < T_; t++) {
        const int cb = t & 1, nb = cb ^ 1;

        // prefetch x(t+1) into registers (lands in smem during phase 2)
        float xpre = 0.0f;
        if (tid < 96 && (t + 1) < T_) {
            const int i = tid >> 5, rr = tid & 31;
            xpre = x[(row0 + rr) * (T_ * 3) + (t + 1) * 3 + i];
        }

        // Phase 1: thread g computes gates[g][row] for all 32 rows.
        // acc[rp] packs rows (2rp, 2rp+1).
        ull acc[16];
        {
            const ulonglong2* xp0 = (const ulonglong2*)(&xsh[cb][0][0]);
            const ulonglong2* xp1 = (const ulonglong2*)(&xsh[cb][1][0]);
            const ulonglong2* xp2 = (const ulonglong2*)(&xsh[cb][2][0]);
#pragma unroll
            for (int q = 0; q < 8; q++) {
                ulonglong2 x0 = xp0[q], x1 = xp1[q], x2 = xp2[q];
                ull a0 = fma2(x0.x, wih2_0, bias2);
                a0     = fma2(x1.x, wih2_1, a0);
                a0     = fma2(x2.x, wih2_2, a0);
                ull a1 = fma2(x0.y, wih2_0, bias2);
                a1     = fma2(x1.y, wih2_1, a1);
                a1     = fma2(x2.y, wih2_2, a1);
                acc[2 * q]     = a0;
                acc[2 * q + 1] = a1;
            }
        }
#pragma unroll
        for (int k = 0; k < H_; k++) {
            const ull w2 = pack2(w[k], w[k]);
            const ulonglong2* hp = (const ulonglong2*)(hsh + k * RT);
#pragma unroll
            for (int q = 0; q < 8; q++) {
                ulonglong2 hv = hp[q];                   // broadcast LDS.128 (4 rows)
                acc[2 * q]     = fma2(hv.x, w2, acc[2 * q]);
                acc[2 * q + 1] = fma2(hv.y, w2, acc[2 * q + 1]);
            }
        }

        // Phase 2: spill gates to smem (pitch 33 -> conflict-free), stage x(t+1).
#pragma unroll
        for (int rp = 0; rp < 16; rp++) {
            float lo, hi;
            unpack2(acc[rp], lo, hi);
            gates[tid * GPITCH + 2 * rp]     = lo;
            gates[tid * GPITCH + 2 * rp + 1] = hi;
        }
        if (tid < 96) xsh[nb][tid >> 5][tid & 31] = xpre;

        __syncthreads();

        // Phase 3: gate nonlinearities + state update. Thread owns 8 (row=r_, unit=j) cells.
#pragma unroll
        for (int p = 0; p < 8; p++) {
            const int j = j0 * 8 + p;
            const float gi = gates[(j)       * GPITCH + r_];
            const float gf = gates[(64  + j) * GPITCH + r_];
            const float gg = gates[(128 + j) * GPITCH + r_];
            const float go = gates[(192 + j) * GPITCH + r_];
            const float ig = sigf(gi);
            const float fg = sigf(gf);
            const float gt = tanhfast(gg);
            const float og = sigf(go);
            const float cn = fmaf(fg, c[p], ig * gt);
            c[p] = cn;
            hsh[j * RT + r_] = og * tanhfast(cn);        // conflict-free STS (banks = r_)
        }

        __syncthreads();

        // Phase 4: decode out[row][t][o] = W_dec[o] . h[row] + b_dec[o]
        if (tid < 96) {
            const int rr = tid & 31;
            const int o  = tid >> 5;
            float s = 0.0f;
#pragma unroll
            for (int k = 0; k < H_; k++)
                s = fmaf(hsh[k * RT + rr], wdec_s[o * H_ + k], s);
            out[(size_t)(row0 + rr) * (T_ * 3) + (size_t)t * 3 + o] = s + bd;
        }
        // no sync needed here: next writers (gates in phase 2, hsh in phase 3)
        // are both behind the next __syncthreads() pair.
    }
}

extern "C" void kernel_launch(void* const* d_in, const int* in_sizes, int n_in,
                              void* d_out, int out_size) {
    const float* x    = (const float*)d_in[0];
    const float* Wih  = (const float*)d_in[1];
    const float* Whh  = (const float*)d_in[2];
    const float* bih  = (const float*)d_in[3];
    const float* bhh  = (const float*)d_in[4];
    const float* Wdec = (const float*)d_in[5];
    const float* bdec = (const float*)d_in[6];
    float* out = (float*)d_out;

    lstm_persistent_kernel<<<B_ / RT, NT>>>(x, Wih, Whh, bih, bhh, Wdec, bdec, out);
}

// round 2
// speedup vs baseline: 1.3190x; 1.3190x over previous
#include <cuda_runtime.h>

// LSTMAnomalyDetector: B=4096, T=512, I=3, H=64 (PyTorch gate order i,f,g,o)
// Persistent CTA: 128 CTAs x 256 threads, 32 batch rows per CTA, all 512 steps on-chip.
//
// Round-2 structure: thread owns (1 unit x 8 rows), computes ALL 4 gate types itself.
//  - no gates smem round trip, ONE barrier per step
//  - W_hh pre-duplicated in smem as (w,w) float2 pairs -> fma.rn.f32x2 with no packing MOVs
//  - per k: 4 LDS.128 + 16 fma2  (was 8 LDS + 16 fma2 + pack)

#define B_  4096
#define T_  512
#define H_  64
#define RT  32       // rows per CTA
#define NT  256      // threads per CTA
#define HP  36       // hsh row pitch in floats (16B-aligned, conflict-light)

typedef unsigned long long ull;

__device__ __forceinline__ float tanhfast(float x) {
    float y; asm("tanh.approx.f32 %0, %1;" : "=f"(y) : "f"(x)); return y;
}
__device__ __forceinline__ float sigf(float x) {
    return fmaf(0.5f, tanhfast(0.5f * x), 0.5f);
}
__device__ __forceinline__ ull pack2(float a, float b) {
    ull r; asm("mov.b64 %0, {%1, %2};" : "=l"(r) : "f"(a), "f"(b)); return r;
}
__device__ __forceinline__ void unpack2(ull v, float& lo, float& hi) {
    asm("mov.b64 {%0, %1}, %2;" : "=f"(lo), "=f"(hi) : "l"(v));
}
__device__ __forceinline__ ull fma2(ull a, ull b, ull c) {
    ull d; asm("fma.rn.f32x2 %0, %1, %2, %3;" : "=l"(d) : "l"(a), "l"(b), "l"(c)); return d;
}

struct Smem {
    // W01[k][u] = (w_i dup16B? no: .x = (wi,wi), .y = (wf,wf)); 16B stride in u -> conflict-free
    ulonglong2 W01[H_][H_];   // 64KB  [k][u]: gates i,f duplicated
    ulonglong2 W23[H_][H_];   // 64KB  [k][u]: gates g,o duplicated
    float hsh[2][H_][HP];     // 18KB  [buf][unit][row(pitch 36)]
    float xsh[2][3][RT];      // x double buffer, transposed [i][row]
    float wdec[3][H_];
};
#define SMEM_BYTES ((int)sizeof(Smem))

extern __shared__ char smem_raw[];

__global__ void __launch_bounds__(NT, 1)
lstm_persistent_kernel(const float* __restrict__ x,      // [B, T, 3]
                       const float* __restrict__ Wih,    // [256, 3]
                       const float* __restrict__ Whh,    // [256, 64]
                       const float* __restrict__ bih,    // [256]
                       const float* __restrict__ bhh,    // [256]
                       const float* __restrict__ Wdec,   // [3, 64]
                       const float* __restrict__ bdec,   // [3]
                       float* __restrict__ out)          // [B, T, 3]
{
    Smem* S = (Smem*)smem_raw;
    const int tid  = threadIdx.x;
    const int row0 = blockIdx.x * RT;

    const int u  = tid >> 2;        // unit 0..63 this thread owns
    const int rg = tid & 3;         // row group: rows 8rg .. 8rg+7

    // ---- setup -----------------------------------------------------------
    // Duplicated W_hh tables: W01[k][u] = ((wi,wi),(wf,wf)), W23 = ((wg,wg),(wo,wo))
    for (int idx = tid; idx < H_ * H_; idx += NT) {
        const int k = idx >> 6, uu = idx & 63;
        const float wi = Whh[(0 * H_ + uu) * H_ + k];
        const float wf = Whh[(1 * H_ + uu) * H_ + k];
        const float wg = Whh[(2 * H_ + uu) * H_ + k];
        const float wo = Whh[(3 * H_ + uu) * H_ + k];
        *(float4*)&S->W01[k][uu] = make_float4(wi, wi, wf, wf);
        *(float4*)&S->W23[k][uu] = make_float4(wg, wg, wo, wo);
    }
    for (int i = tid; i < 2 * H_ * HP; i += NT) ((float*)S->hsh)[i] = 0.0f;
    if (tid < 3 * H_) ((float*)S->wdec)[tid] = Wdec[tid];

    // per-thread W_ih (duplicated) and bias, in registers
    ull wih2[4][3], biasp[4];
#pragma unroll
    for (int gt = 0; gt < 4; gt++) {
        const int g = gt * H_ + u;
        const float b = bih[g] + bhh[g];
        biasp[gt] = pack2(b, b);
#pragma unroll
        for (int i = 0; i < 3; i++) {
            const float wv = Wih[g * 3 + i];
            wih2[gt][i] = pack2(wv, wv);
        }
    }

    // decode / x-staging roles (threads 0..95)
    const int dro = tid >> 5;       // output comp / x comp (0..2)
    const int drr = tid & 31;       // row
    float bd = 0.0f;
    if (tid < 96) {
        bd = bdec[dro];
        S->xsh[0][dro][drr] = x[((size_t)(row0 + drr) * T_ + 0) * 3 + dro];
    }

    float c[8];
#pragma unroll
    for (int p = 0; p < 8; p++) c[p] = 0.0f;

    __syncthreads();

    // ---- timestep loop -----------------------------------------------------
    for (int t = 0; t < T_; t++) {
        const int A = t & 1, Bb = A ^ 1;

        // prefetch x(t+1) (consumed late, latency hidden under matvec)
        float xp = 0.0f;
        if (tid < 96 && (t + 1) < T_)
            xp = x[((size_t)(row0 + drr) * T_ + (t + 1)) * 3 + dro];

        // decode previous step's h: out[., t-1, .]
        if (t > 0 && tid < 96) {
            const float* hp_ = &S->hsh[A][0][drr];
            const float* wd  = &S->wdec[dro][0];
            float s0 = 0.f, s1 = 0.f, s2 = 0.f, s3 = 0.f;
#pragma unroll 4
            for (int k = 0; k < H_; k += 4) {
                s0 = fmaf(hp_[(k + 0) * HP], wd[k + 0], s0);
                s1 = fmaf(hp_[(k + 1) * HP], wd[k + 1], s1);
                s2 = fmaf(hp_[(k + 2) * HP], wd[k + 2], s2);
                s3 = fmaf(hp_[(k + 3) * HP], wd[k + 3], s3);
            }
            out[((size_t)(row0 + drr) * T_ + (t - 1)) * 3 + dro] = (s0 + s1) + (s2 + s3) + bd;
        }

        // accumulator init: bias + W_ih * x(t)
        ull a0[4], a1[4], a2[4], a3[4];
#pragma unroll
        for (int rp = 0; rp < 4; rp++) { a0[rp] = biasp[0]; a1[rp] = biasp[1]; a2[rp] = biasp[2]; a3[rp] = biasp[3]; }
#pragma unroll
        for (int i = 0; i < 3; i++) {
            const ulonglong2 xa = *(const ulonglong2*)&S->xsh[A][i][8 * rg];
            const ulonglong2 xb = *(const ulonglong2*)&S->xsh[A][i][8 * rg + 4];
            ull xv[4]; xv[0] = xa.x; xv[1] = xa.y; xv[2] = xb.x; xv[3] = xb.y;
#pragma unroll
            for (int rp = 0; rp < 4; rp++) {
                a0[rp] = fma2(xv[rp], wih2[0][i], a0[rp]);
                a1[rp] = fma2(xv[rp], wih2[1][i], a1[rp]);
                a2[rp] = fma2(xv[rp], wih2[2][i], a2[rp]);
                a3[rp] = fma2(xv[rp], wih2[3][i], a3[rp]);
            }
        }

        // recurrent matvec: gates[gt][u][rows] += sum_k Whh * h(t-1)
        {
            const float* hrow = &S->hsh[A][0][8 * rg];
            const ulonglong2* w01p = &S->W01[0][u];
            const ulonglong2* w23p = &S->W23[0][u];
#pragma unroll 8
            for (int k = 0; k < H_; k++) {
                const ulonglong2 hA = *(const ulonglong2*)(hrow);       // rows 8rg..8rg+3
                const ulonglong2 hB = *(const ulonglong2*)(hrow + 4);   // rows 8rg+4..+7
                const ulonglong2 w01 = w01p[k * H_];
                const ulonglong2 w23 = w23p[k * H_];
                a0[0] = fma2(hA.x, w01.x, a0[0]);
                a0[1] = fma2(hA.y, w01.x, a0[1]);
                a0[2] = fma2(hB.x, w01.x, a0[2]);
                a0[3] = fma2(hB.y, w01.x, a0[3]);
                a1[0] = fma2(hA.x, w01.y, a1[0]);
                a1[1] = fma2(hA.y, w01.y, a1[1]);
                a1[2] = fma2(hB.x, w01.y, a1[2]);
                a1[3] = fma2(hB.y, w01.y, a1[3]);
                a2[0] = fma2(hA.x, w23.x, a2[0]);
                a2[1] = fma2(hA.y, w23.x, a2[1]);
                a2[2] = fma2(hB.x, w23.x, a2[2]);
                a2[3] = fma2(hB.y, w23.x, a2[3]);
                a3[0] = fma2(hA.x, w23.y, a3[0]);
                a3[1] = fma2(hA.y, w23.y, a3[1]);
                a3[2] = fma2(hB.x, w23.y, a3[2]);
                a3[3] = fma2(hB.y, w23.y, a3[3]);
                hrow += HP;
            }
        }

        // nonlinearities + state update, directly on accumulators
        float hout[8];
#pragma unroll
        for (int rp = 0; rp < 4; rp++) {
            float gi0, gi1, gf0, gf1, gg0, gg1, go0, go1;
            unpack2(a0[rp], gi0, gi1);
            unpack2(a1[rp], gf0, gf1);
            unpack2(a2[rp], gg0, gg1);
            unpack2(a3[rp], go0, go1);
            {
                const float ig = sigf(gi0), fg = sigf(gf0), gg = tanhfast(gg0), og = sigf(go0);
                const float cn = fmaf(fg, c[2 * rp], ig * gg);
                c[2 * rp] = cn;
                hout[2 * rp] = og * tanhfast(cn);
            }
            {
                const float ig = sigf(gi1), fg = sigf(gf1), gg = tanhfast(gg1), og = sigf(go1);
                const float cn = fmaf(fg, c[2 * rp + 1], ig * gg);
                c[2 * rp + 1] = cn;
                hout[2 * rp + 1] = og * tanhfast(cn);
            }
        }
        {
            float* hd = &S->hsh[Bb][u][8 * rg];
            *(float4*)(hd)     = make_float4(hout[0], hout[1], hout[2], hout[3]);
            *(float4*)(hd + 4) = make_float4(hout[4], hout[5], hout[6], hout[7]);
        }

        // stage x(t+1)
        if (tid < 96) S->xsh[Bb][dro][drr] = xp;

        __syncthreads();
    }

    // epilogue: decode h(T-1) (lives in buffer 0)
    if (tid < 96) {
        const float* hp_ = &S->hsh[0][0][drr];
        const float* wd  = &S->wdec[dro][0];
        float s0 = 0.f, s1 = 0.f, s2 = 0.f, s3 = 0.f;
#pragma unroll 4
        for (int k = 0; k < H_; k += 4) {
            s0 = fmaf(hp_[(k + 0) * HP], wd[k + 0], s0);
            s1 = fmaf(hp_[(k + 1) * HP], wd[k + 1], s1);
            s2 = fmaf(hp_[(k + 2) * HP], wd[k + 2], s2);
            s3 = fmaf(hp_[(k + 3) * HP], wd[k + 3], s3);
        }
        out[((size_t)(row0 + drr) * T_ + (T_ - 1)) * 3 + dro] = (s0 + s1) + (s2 + s3) + bd;
    }
}

extern "C" void kernel_launch(void* const* d_in, const int* in_sizes, int n_in,
                              void* d_out, int out_size) {
    const float* x    = (const float*)d_in[0];
    const float* Wih  = (const float*)d_in[1];
    const float* Whh  = (const float*)d_in[2];
    const float* bih  = (const float*)d_in[3];
    const float* bhh  = (const float*)d_in[4];
    const float* Wdec = (const float*)d_in[5];
    const float* bdec = (const float*)d_in[6];
    float* out = (float*)d_out;

    cudaFuncSetAttribute(lstm_persistent_kernel,
                         cudaFuncAttributeMaxDynamicSharedMemorySize, SMEM_BYTES);
    lstm_persistent_kernel<<<B_ / RT, NT, SMEM_BYTES>>>(x, Wih, Whh, bih, bhh, Wdec, bdec, out);
}